// round 13
// baseline (speedup 1.0000x reference)
#include <cuda_runtime.h>
#include <cuda_fp16.h>
#include <cstdint>

// ---------------------------------------------------------------------------
// Net_22625887715641 on GB300 (sm_103a, compiled as compute_103 base ISA)
//
//   K1 feat_kernel : 11x11(x3) valid convs -> g_feat[2][32][384][384]
//   K2 norm_kernel : channel normalize; v=0 -> d_out (x1),
//                    v=1 in place + f16 copy g_xp16 (implicit GEMM B)
//   K3 packA       : A[(o,w)][(p,q)] masked/shifted x1 -> f16 fragment order
//   K4 gemm_kernel : mma.sync m16n8k16 f16->f32 GEMM 736x736x139008 (16-align
//                    masked out of a 768x768 grid), split-K x8, CTA 128x128,
//                    A via LDG.128 fragments, B via 4-stage cp.async, 2 CTA/SM
//   K5 assemble    : g_acc -> x2 permute + scale
// ---------------------------------------------------------------------------

#define X1_ELEMS   (32 * 384 * 384)          // 4718592
#define GEMM_K     139008                    // 362*384
#define K_ITERS64  2172                      // GEMM_K / 64
#define SPLITS     8
#define IPS        272                       // ceil(2172/8); last split 268
#define N_MCHUNK   46                        // ceil(736/16); rows 736+ masked off

// A in fragment order: index ((mchunk*2172 + kt)*4 + ks)*32 + lane -> uint4
__device__ __align__(16) uint4  g_Af[(size_t)48 * K_ITERS64 * 128]; // 48 slots (padded)
__device__ float   g_feat[2 * X1_ELEMS];
__device__ __align__(16) __half g_xp16[34 * 147456];
__device__ float   g_acc[768 * 768];
__constant__ float c_ft[16 * 3 * 11 * 11];
__constant__ float c_fn[16 * 11 * 11];

// ===================== PTX helpers ========================================
__device__ __forceinline__ uint32_t smem_u32(const void* p) {
    uint32_t a;
    asm("{ .reg .u64 t; cvta.to.shared.u64 t, %1; cvt.u32.u64 %0, t; }"
        : "=r"(a) : "l"(p));
    return a;
}
#define CP_ASYNC16(dst, src) \
    asm volatile("cp.async.cg.shared.global [%0], [%1], 16;" \
                 :: "r"(dst), "l"(src) : "memory")
#define CP_COMMIT() asm volatile("cp.async.commit_group;" ::: "memory")
#define CP_WAIT2()  asm volatile("cp.async.wait_group 2;" ::: "memory")

#define LDSM4(r0, r1, r2, r3, addr) \
    asm volatile("ldmatrix.sync.aligned.m8n8.x4.shared.b16 {%0,%1,%2,%3}, [%4];" \
                 : "=r"(r0), "=r"(r1), "=r"(r2), "=r"(r3) : "r"(addr))

#define MMA16816(D, a0, a1, a2, a3, b0, b1) \
    asm volatile("mma.sync.aligned.m16n8k16.row.col.f32.f16.f16.f32 " \
                 "{%0,%1,%2,%3}, {%4,%5,%6,%7}, {%8,%9}, {%0,%1,%2,%3};" \
                 : "+f"((D)[0]), "+f"((D)[1]), "+f"((D)[2]), "+f"((D)[3]) \
                 : "r"(a0), "r"(a1), "r"(a2), "r"(a3), "r"(b0), "r"(b1))

// ===========================================================================
// Kernel 1: features (unchanged, 118us)
// ===========================================================================
__global__ void __launch_bounds__(256) feat_kernel(const float* __restrict__ x0,
                                                   const float* __restrict__ x1in)
{
    __shared__ __align__(16) float s_in[3 * 18 * 76];
    const int v  = blockIdx.z;
    const float* src = v ? x1in : x0;
    const int y0 = blockIdx.y * 8;
    const int xb = blockIdx.x * 64;

    for (int e = threadIdx.x; e < 3 * 18 * 74; e += 256) {
        int t = e / (18 * 74);
        int rem = e % (18 * 74);
        int r = rem / 74;
        int cc = rem % 74;
        s_in[(t * 18 + r) * 76 + cc] = src[(t * 394 + (y0 + r)) * 394 + xb + cc];
    }
    __syncthreads();

    for (int it = 0; it < 8; it++) {
        int task = it * 256 + threadIdx.x;
        int c = task >> 6;
        int rem = task & 63;
        int yy = rem >> 3;
        int xc = rem & 7;

        float acc[8];
#pragma unroll
        for (int k = 0; k < 8; k++) acc[k] = 0.f;

        if (c < 16) {
            const float* fb = c_ft + c * 363;
            for (int t = 0; t < 3; t++) {
                for (int i = 0; i < 11; i++) {
                    const float4* rowp = reinterpret_cast<const float4*>(
                        &s_in[(t * 18 + (yy + i)) * 76 + xc * 8]);
                    float w[20];
#pragma unroll
                    for (int m = 0; m < 5; m++) {
                        float4 f4 = rowp[m];
                        w[4 * m] = f4.x; w[4 * m + 1] = f4.y;
                        w[4 * m + 2] = f4.z; w[4 * m + 3] = f4.w;
                    }
#pragma unroll
                    for (int j = 0; j < 11; j++) {
                        float f = fb[t * 121 + i * 11 + j];
#pragma unroll
                        for (int k = 0; k < 8; k++) acc[k] += f * w[j + k];
                    }
                }
            }
#pragma unroll
            for (int k = 0; k < 8; k++) acc[k] = fmaxf(acc[k], 0.f) * 0.5f;
        } else {
            const float* fb = c_fn + (c - 16) * 121;
            const int t = 2;
            for (int i = 0; i < 11; i++) {
                const float4* rowp = reinterpret_cast<const float4*>(
                    &s_in[(t * 18 + (yy + i)) * 76 + xc * 8]);
                float w[20];
#pragma unroll
                for (int m = 0; m < 5; m++) {
                    float4 f4 = rowp[m];
                    w[4 * m] = f4.x; w[4 * m + 1] = f4.y;
                    w[4 * m + 2] = f4.z; w[4 * m + 3] = f4.w;
                }
#pragma unroll
                for (int j = 0; j < 11; j++) {
                    float f = fb[i * 11 + j];
#pragma unroll
                    for (int k = 0; k < 8; k++) acc[k] += f * w[j + k];
                }
            }
#pragma unroll
            for (int k = 0; k < 8; k++) acc[k] = fmaxf(acc[k], 0.f);
        }

        float* dst = g_feat + ((v * 32 + c) * 384 + (y0 + yy)) * 384 + xb + xc * 8;
#pragma unroll
        for (int k = 0; k < 8; k++) dst[k] = acc[k];
    }
}

// ===========================================================================
// Kernel 2: channel normalization (+ f16 emission of x1_prev)
// ===========================================================================
__global__ void norm_kernel(float* __restrict__ out_x1)
{
    int idx = blockIdx.x * blockDim.x + threadIdx.x;
    if (idx >= 2 * 147456) return;
    int v = idx / 147456;
    int pix = idx % 147456;
    float* base = g_feat + v * X1_ELEMS;

    float s = 0.f;
#pragma unroll
    for (int c = 0; c < 32; c++) s += base[c * 147456 + pix];
    float inv = 1.0f / (s + 2.2204460492503131e-16f);

    if (v == 0) {
#pragma unroll
        for (int c = 0; c < 32; c++)
            out_x1[c * 147456 + pix] = base[c * 147456 + pix] * inv;
    } else {
#pragma unroll
        for (int c = 0; c < 32; c++) {
            float val = base[c * 147456 + pix] * inv;
            base[c * 147456 + pix] = val;
            g_xp16[c * 147456 + pix] = __float2half_rn(val);
        }
    }
}

// ===========================================================================
// Kernel 3: pack A into MMA fragment order (46 mchunks = rows 0..735).
// ===========================================================================
__device__ __forceinline__ float fetchA(const float* __restrict__ x1,
                                        int o, int w, int p, int q)
{
    if (q >= w && q < 362 + w)
        return x1[o * 147456 + (11 + p) * 384 + 11 + q - w];
    return 0.f;
}

__global__ void __launch_bounds__(128) packA_kernel(const float* __restrict__ x1)
{
    const int kt = blockIdx.x;         // 0..2171
    const int mc = blockIdx.y;         // 0..45
    const int ks = threadIdx.x >> 5;   // 0..3
    const int lane = threadIdx.x & 31;
    const int g = lane >> 2, t4 = lane & 3;

    const int r0 = mc * 16 + g;
    const int r1 = r0 + 8;
    const int p  = kt / 6;
    const int q0 = 64 * (kt % 6) + ks * 16 + t4 * 2;

    int o0 = r0 / 23, w0 = r0 % 23;
    int o1 = r1 / 23, w1 = r1 % 23;
    bool v1 = (r1 < 736);

    uint4 out;
    __half2 h;
    h = __floats2half2_rn(fetchA(x1, o0, w0, p, q0),
                          fetchA(x1, o0, w0, p, q0 + 1));
    out.x = *reinterpret_cast<uint32_t*>(&h);
    h = v1 ? __floats2half2_rn(fetchA(x1, o1, w1, p, q0),
                               fetchA(x1, o1, w1, p, q0 + 1))
           : __floats2half2_rn(0.f, 0.f);
    out.y = *reinterpret_cast<uint32_t*>(&h);
    h = __floats2half2_rn(fetchA(x1, o0, w0, p, q0 + 8),
                          fetchA(x1, o0, w0, p, q0 + 9));
    out.z = *reinterpret_cast<uint32_t*>(&h);
    h = v1 ? __floats2half2_rn(fetchA(x1, o1, w1, p, q0 + 8),
                               fetchA(x1, o1, w1, p, q0 + 9))
           : __floats2half2_rn(0.f, 0.f);
    out.w = *reinterpret_cast<uint32_t*>(&h);

    g_Af[(((size_t)mc * K_ITERS64 + kt) * 4 + ks) * 32 + lane] = out;
}

// ===========================================================================
// Kernel 4: GEMM. grid (Nt:6, Mt:6, split:8), 256 threads, 2 CTAs/SM.
// CTA tile 128x128, warp tile 32x64 (8 warps: 4 wm x 2 wn), kc=64.
// Padding masked at warp granularity: mok (rows >= 736) skips A/MMA entirely;
// pmax clips the p loop (cols >= 736).
// ===========================================================================
#define B_STAGE_B  18432            // 128*144
#define GEMM_SMEM  (4 * B_STAGE_B)  // 73728

__global__ void __launch_bounds__(256, 2) gemm_kernel()
{
    extern __shared__ char smem[];
    const uint32_t sb = smem_u32(smem);
    const int tid = threadIdx.x;
    const int lane = tid & 31, wid = tid >> 5;
    const int Nt = blockIdx.x, Mt = blockIdx.y, sp = blockIdx.z;
    const int wm = wid & 3, wn = wid >> 2;   // warp tile: rows wm*32, cols wn*64
    const int g = lane >> 2, t4 = lane & 3;

    // ---- padding masks (warp-uniform) ----
    const bool mok = (Mt * 128 + wm * 32) < 736;          // false only Mt=5,wm=3
    int pmax = (736 - Nt * 128 - wn * 64 + 15) >> 4;      // 16-col MMA p-blocks
    if (pmax > 4) pmax = 4;
    if (pmax < 0) pmax = 0;

    // ---- B cp.async mapping: 4 chunks (16B) per thread per tile ----
    const int lr = tid >> 3;         // 0..31
    const int lc = tid & 7;          // 0..7
    const __half* gB0[4];
#pragma unroll
    for (int j = 0; j < 4; j++) {
        int n = Nt * 128 + lr + 32 * j;
        gB0[j] = g_xp16 + (size_t)(n / 23) * 147456 + (n % 23) * 384 + lc * 8;
    }
    const uint32_t dOff = (uint32_t)(lr * 144 + lc * 16);

    // ---- A fragment pointers (per warp, mt = 0/1) ----
    const int mc0 = Mt * 8 + wm * 2;
    const uint4* pA0 = g_Af + ((size_t)(mc0 + 0) * K_ITERS64) * 128 + lane;
    const uint4* pA1 = g_Af + ((size_t)(mc0 + 1) * K_ITERS64) * 128 + lane;

    const int k0 = sp * IPS;
    const int k1 = (k0 + IPS < K_ITERS64) ? (k0 + IPS) : K_ITERS64;

#define LOAD_B(kt, b) do {                                                     \
        size_t _ko = (size_t)(kt) * 64;                                        \
        uint32_t _bB = sb + (b) * B_STAGE_B;                                   \
        _Pragma("unroll")                                                      \
        for (int _j = 0; _j < 4; _j++)                                         \
            CP_ASYNC16(_bB + dOff + _j * (32 * 144), gB0[_j] + _ko);           \
    } while (0)

    LOAD_B(k0,     (k0) & 3);     CP_COMMIT();
    LOAD_B(k0 + 1, (k0 + 1) & 3); CP_COMMIT();
    LOAD_B(k0 + 2, (k0 + 2) & 3); CP_COMMIT();

    float acc[2][8][4];
#pragma unroll
    for (int mt = 0; mt < 2; mt++)
#pragma unroll
        for (int nt = 0; nt < 8; nt++)
#pragma unroll
            for (int e = 0; e < 4; e++) acc[mt][nt][e] = 0.f;

    // ---- per-lane ldmatrix offset for B (bytes) ----
    const int matq = lane >> 3, rin = lane & 7;
    const uint32_t offB = (uint32_t)((((matq >> 1) * 8 + rin) * 144) + (matq & 1) * 16);
    const uint32_t bRow = (uint32_t)(wn * 64) * 144;

    uint32_t Bf[4][4];
    uint4 Acur0, Acur1, Anxt0, Anxt1;
    Acur0 = make_uint4(0, 0, 0, 0); Acur1 = Acur0;

    // prologue: A fragments for (k0, ks=0)
    if (mok) {
        Acur0 = __ldg(pA0 + ((size_t)k0 * 4 + 0) * 32);
        Acur1 = __ldg(pA1 + ((size_t)k0 * 4 + 0) * 32);
    }

    for (int kt = k0; kt < k1; kt++) {
        CP_WAIT2();          // tile kt resident (kt+1, kt+2 may be in flight)
        __syncthreads();     // all warps done reading slot (kt+3)&3's old tile
        if (kt + 3 < k1) LOAD_B(kt + 3, (kt + 3) & 3);
        CP_COMMIT();         // unconditional (possibly empty group)

        const uint32_t cB = sb + (kt & 3) * B_STAGE_B;

#pragma unroll
        for (int ks = 0; ks < 4; ks++) {
            // prefetch next A fragments (next ks, or next kt's ks=0)
            if (mok) {
                int nkt = (ks < 3) ? kt : ((kt + 1 < k1) ? kt + 1 : kt);
                int nks = (ks + 1) & 3;
                size_t aoff = ((size_t)nkt * 4 + nks) * 32;
                Anxt0 = __ldg(pA0 + aoff);
                Anxt1 = __ldg(pA1 + aoff);
            }
#pragma unroll
            for (int p = 0; p < 4; p++) {
                if (mok && p < pmax) {
                    LDSM4(Bf[p][0], Bf[p][1], Bf[p][2], Bf[p][3],
                          cB + bRow + p * (16 * 144) + ks * 32 + offB);
                    MMA16816(acc[0][2 * p],     Acur0.x, Acur0.y, Acur0.z, Acur0.w,
                             Bf[p][0], Bf[p][1]);
                    MMA16816(acc[0][2 * p + 1], Acur0.x, Acur0.y, Acur0.z, Acur0.w,
                             Bf[p][2], Bf[p][3]);
                    MMA16816(acc[1][2 * p],     Acur1.x, Acur1.y, Acur1.z, Acur1.w,
                             Bf[p][0], Bf[p][1]);
                    MMA16816(acc[1][2 * p + 1], Acur1.x, Acur1.y, Acur1.z, Acur1.w,
                             Bf[p][2], Bf[p][3]);
                }
            }
            Acur0 = Anxt0;
            Acur1 = Anxt1;
        }
    }

    // ---- epilogue: atomicAdd into g_acc (split-K reduction) ----
    if (mok) {
        const int row0 = Mt * 128 + wm * 32;
        const int col0 = Nt * 128 + wn * 64;
#pragma unroll
        for (int mt = 0; mt < 2; mt++) {
            int r_lo = row0 + mt * 16 + g;
            int r_hi = r_lo + 8;
#pragma unroll
            for (int nt = 0; nt < 8; nt++) {
                int c = col0 + nt * 8 + 2 * t4;
                bool c0ok = (c < 736), c1ok = (c + 1 < 736);
                if (r_lo < 736) {
                    if (c0ok) atomicAdd(&g_acc[r_lo * 768 + c],     acc[mt][nt][0]);
                    if (c1ok) atomicAdd(&g_acc[r_lo * 768 + c + 1], acc[mt][nt][1]);
                }
                if (r_hi < 736) {
                    if (c0ok) atomicAdd(&g_acc[r_hi * 768 + c],     acc[mt][nt][2]);
                    if (c1ok) atomicAdd(&g_acc[r_hi * 768 + c + 1], acc[mt][nt][3]);
                }
            }
        }
    }
#undef LOAD_B
}

// ===========================================================================
// Kernel 5: assemble x2 from g_acc with permutation + scale
// ===========================================================================
__global__ void assemble_kernel(float* __restrict__ out_x2)
{
    int i = blockIdx.x * 256 + threadIdx.x;
    if (i >= 32 * 32 * 23 * 23) return;
    int w = i % 23;
    int t = i / 23;
    int h = t % 23; t /= 23;
    int d = t % 32;
    int o = t / 32;
    out_x2[i] = g_acc[(o * 23 + w) * 768 + (d * 23 + h)] * (1.0f / 131044.0f);
}

// ===========================================================================
// Launch
// ===========================================================================
extern "C" void kernel_launch(void* const* d_in, const int* in_sizes, int n_in,
                              void* d_out, int out_size)
{
    const float* x  = (const float*)d_in[0];
    const float* xp = (const float*)d_in[1];
    float* out = (float*)d_out;

    void *aft = nullptr, *afn = nullptr, *aacc = nullptr;
    cudaGetSymbolAddress(&aft, c_ft);
    cudaGetSymbolAddress(&afn, c_fn);
    cudaGetSymbolAddress(&aacc, g_acc);
    cudaMemcpyAsync(aft, d_in[2], 5808 * sizeof(float), cudaMemcpyDeviceToDevice, 0);
    cudaMemcpyAsync(afn, d_in[3], 1936 * sizeof(float), cudaMemcpyDeviceToDevice, 0);
    cudaMemsetAsync(aacc, 0, 768 * 768 * sizeof(float), 0);

    dim3 g1(6, 48, 2);
    feat_kernel<<<g1, 256>>>(x, xp);

    norm_kernel<<<(2 * 147456 + 255) / 256, 256>>>(out);

    dim3 g3(K_ITERS64, N_MCHUNK);
    packA_kernel<<<g3, 128>>>(out);

    static bool attr_set = false;
    if (!attr_set) {
        cudaFuncSetAttribute(gemm_kernel, cudaFuncAttributeMaxDynamicSharedMemorySize,
                             GEMM_SMEM);
        attr_set = true;
    }
    dim3 g4(6, 6, SPLITS);
    gemm_kernel<<<g4, 256, GEMM_SMEM>>>();

    assemble_kernel<<<(32 * 32 * 23 * 23 + 255) / 256, 256>>>(out + X1_ELEMS);
}

// round 14
// speedup vs baseline: 1.3168x; 1.3168x over previous
#include <cuda_runtime.h>
#include <cuda_fp16.h>
#include <cstdint>

// ---------------------------------------------------------------------------
// Net_22625887715641 on GB300 (sm_103a, compiled as compute_103 base ISA)
//
//   K1 feat_kernel : 11x11(x3) valid convs -> g_feat[2][32][384][384]
//   K2 norm_kernel : channel normalize; v=0 -> d_out (x1),
//                    v=1 in place + f16 copy g_xp16 (implicit GEMM B)
//   K3 packA       : A[(o,w)][(p,q)] masked/shifted x1 -> f16 fragment order
//                    (46 mchunks; slots 46-47 stay zero-initialized)
//   K4 gemm_kernel : mma.sync m16n8k16 f16->f32 GEMM 768x768x139008,
//                    split-K x8, CTA 128x128 / 256 thr / warp tile 32x64,
//                    A via LDG.128 fragments (no smem), B via 4-stage
//                    cp.async smem, 2 CTAs/SM  [R12 mainloop, branch-free]
//   K5 assemble    : g_acc -> x2 permute + scale
// ---------------------------------------------------------------------------

#define X1_ELEMS   (32 * 384 * 384)          // 4718592
#define GEMM_K     139008                    // 362*384
#define K_ITERS64  2172                      // GEMM_K / 64
#define SPLITS     8
#define IPS        272                       // ceil(2172/8); last split 268
#define N_MCHUNK   46                        // rows 0..735 packed; 46,47 zero

// A in fragment order: index ((mchunk*2172 + kt)*4 + ks)*32 + lane -> uint4
__device__ __align__(16) uint4  g_Af[(size_t)48 * K_ITERS64 * 128]; // ~213MB
__device__ float   g_feat[2 * X1_ELEMS];
__device__ __align__(16) __half g_xp16[34 * 147456];
__device__ float   g_acc[768 * 768];
__constant__ float c_ft[16 * 3 * 11 * 11];
__constant__ float c_fn[16 * 11 * 11];

// ===================== PTX helpers ========================================
__device__ __forceinline__ uint32_t smem_u32(const void* p) {
    uint32_t a;
    asm("{ .reg .u64 t; cvta.to.shared.u64 t, %1; cvt.u32.u64 %0, t; }"
        : "=r"(a) : "l"(p));
    return a;
}
#define CP_ASYNC16(dst, src) \
    asm volatile("cp.async.cg.shared.global [%0], [%1], 16;" \
                 :: "r"(dst), "l"(src) : "memory")
#define CP_COMMIT() asm volatile("cp.async.commit_group;" ::: "memory")
#define CP_WAIT2()  asm volatile("cp.async.wait_group 2;" ::: "memory")

#define LDSM4(r0, r1, r2, r3, addr) \
    asm volatile("ldmatrix.sync.aligned.m8n8.x4.shared.b16 {%0,%1,%2,%3}, [%4];" \
                 : "=r"(r0), "=r"(r1), "=r"(r2), "=r"(r3) : "r"(addr))

#define MMA16816(D, a0, a1, a2, a3, b0, b1) \
    asm volatile("mma.sync.aligned.m16n8k16.row.col.f32.f16.f16.f32 " \
                 "{%0,%1,%2,%3}, {%4,%5,%6,%7}, {%8,%9}, {%0,%1,%2,%3};" \
                 : "+f"((D)[0]), "+f"((D)[1]), "+f"((D)[2]), "+f"((D)[3]) \
                 : "r"(a0), "r"(a1), "r"(a2), "r"(a3), "r"(b0), "r"(b1))

// ===========================================================================
// Kernel 1: features (unchanged, 118us)
// ===========================================================================
__global__ void __launch_bounds__(256) feat_kernel(const float* __restrict__ x0,
                                                   const float* __restrict__ x1in)
{
    __shared__ __align__(16) float s_in[3 * 18 * 76];
    const int v  = blockIdx.z;
    const float* src = v ? x1in : x0;
    const int y0 = blockIdx.y * 8;
    const int xb = blockIdx.x * 64;

    for (int e = threadIdx.x; e < 3 * 18 * 74; e += 256) {
        int t = e / (18 * 74);
        int rem = e % (18 * 74);
        int r = rem / 74;
        int cc = rem % 74;
        s_in[(t * 18 + r) * 76 + cc] = src[(t * 394 + (y0 + r)) * 394 + xb + cc];
    }
    __syncthreads();

    for (int it = 0; it < 8; it++) {
        int task = it * 256 + threadIdx.x;
        int c = task >> 6;
        int rem = task & 63;
        int yy = rem >> 3;
        int xc = rem & 7;

        float acc[8];
#pragma unroll
        for (int k = 0; k < 8; k++) acc[k] = 0.f;

        if (c < 16) {
            const float* fb = c_ft + c * 363;
            for (int t = 0; t < 3; t++) {
                for (int i = 0; i < 11; i++) {
                    const float4* rowp = reinterpret_cast<const float4*>(
                        &s_in[(t * 18 + (yy + i)) * 76 + xc * 8]);
                    float w[20];
#pragma unroll
                    for (int m = 0; m < 5; m++) {
                        float4 f4 = rowp[m];
                        w[4 * m] = f4.x; w[4 * m + 1] = f4.y;
                        w[4 * m + 2] = f4.z; w[4 * m + 3] = f4.w;
                    }
#pragma unroll
                    for (int j = 0; j < 11; j++) {
                        float f = fb[t * 121 + i * 11 + j];
#pragma unroll
                        for (int k = 0; k < 8; k++) acc[k] += f * w[j + k];
                    }
                }
            }
#pragma unroll
            for (int k = 0; k < 8; k++) acc[k] = fmaxf(acc[k], 0.f) * 0.5f;
        } else {
            const float* fb = c_fn + (c - 16) * 121;
            const int t = 2;
            for (int i = 0; i < 11; i++) {
                const float4* rowp = reinterpret_cast<const float4*>(
                    &s_in[(t * 18 + (yy + i)) * 76 + xc * 8]);
                float w[20];
#pragma unroll
                for (int m = 0; m < 5; m++) {
                    float4 f4 = rowp[m];
                    w[4 * m] = f4.x; w[4 * m + 1] = f4.y;
                    w[4 * m + 2] = f4.z; w[4 * m + 3] = f4.w;
                }
#pragma unroll
                for (int j = 0; j < 11; j++) {
                    float f = fb[i * 11 + j];
#pragma unroll
                    for (int k = 0; k < 8; k++) acc[k] += f * w[j + k];
                }
            }
#pragma unroll
            for (int k = 0; k < 8; k++) acc[k] = fmaxf(acc[k], 0.f);
        }

        float* dst = g_feat + ((v * 32 + c) * 384 + (y0 + yy)) * 384 + xb + xc * 8;
#pragma unroll
        for (int k = 0; k < 8; k++) dst[k] = acc[k];
    }
}

// ===========================================================================
// Kernel 2: channel normalization (+ f16 emission of x1_prev)
// ===========================================================================
__global__ void norm_kernel(float* __restrict__ out_x1)
{
    int idx = blockIdx.x * blockDim.x + threadIdx.x;
    if (idx >= 2 * 147456) return;
    int v = idx / 147456;
    int pix = idx % 147456;
    float* base = g_feat + v * X1_ELEMS;

    float s = 0.f;
#pragma unroll
    for (int c = 0; c < 32; c++) s += base[c * 147456 + pix];
    float inv = 1.0f / (s + 2.2204460492503131e-16f);

    if (v == 0) {
#pragma unroll
        for (int c = 0; c < 32; c++)
            out_x1[c * 147456 + pix] = base[c * 147456 + pix] * inv;
    } else {
#pragma unroll
        for (int c = 0; c < 32; c++) {
            float val = base[c * 147456 + pix] * inv;
            base[c * 147456 + pix] = val;
            g_xp16[c * 147456 + pix] = __float2half_rn(val);
        }
    }
}

// ===========================================================================
// Kernel 3: pack A into MMA fragment order (46 mchunks = rows 0..735).
// ===========================================================================
__device__ __forceinline__ float fetchA(const float* __restrict__ x1,
                                        int o, int w, int p, int q)
{
    if (q >= w && q < 362 + w)
        return x1[o * 147456 + (11 + p) * 384 + 11 + q - w];
    return 0.f;
}

__global__ void __launch_bounds__(128) packA_kernel(const float* __restrict__ x1)
{
    const int kt = blockIdx.x;         // 0..2171
    const int mc = blockIdx.y;         // 0..45
    const int ks = threadIdx.x >> 5;   // 0..3
    const int lane = threadIdx.x & 31;
    const int g = lane >> 2, t4 = lane & 3;

    const int r0 = mc * 16 + g;
    const int r1 = r0 + 8;
    const int p  = kt / 6;
    const int q0 = 64 * (kt % 6) + ks * 16 + t4 * 2;

    int o0 = r0 / 23, w0 = r0 % 23;
    int o1 = r1 / 23, w1 = r1 % 23;
    bool v1 = (r1 < 736);

    uint4 out;
    __half2 h;
    h = __floats2half2_rn(fetchA(x1, o0, w0, p, q0),
                          fetchA(x1, o0, w0, p, q0 + 1));
    out.x = *reinterpret_cast<uint32_t*>(&h);
    h = v1 ? __floats2half2_rn(fetchA(x1, o1, w1, p, q0),
                               fetchA(x1, o1, w1, p, q0 + 1))
           : __floats2half2_rn(0.f, 0.f);
    out.y = *reinterpret_cast<uint32_t*>(&h);
    h = __floats2half2_rn(fetchA(x1, o0, w0, p, q0 + 8),
                          fetchA(x1, o0, w0, p, q0 + 9));
    out.z = *reinterpret_cast<uint32_t*>(&h);
    h = v1 ? __floats2half2_rn(fetchA(x1, o1, w1, p, q0 + 8),
                               fetchA(x1, o1, w1, p, q0 + 9))
           : __floats2half2_rn(0.f, 0.f);
    out.w = *reinterpret_cast<uint32_t*>(&h);

    g_Af[(((size_t)mc * K_ITERS64 + kt) * 4 + ks) * 32 + lane] = out;
}

// ===========================================================================
// Kernel 4: GEMM (R12 mainloop, branch-free). grid (Nt:6, Mt:6, split:8),
// 256 threads, 2 CTAs/SM. CTA tile 128x128, warp tile 32x64, kc=64.
// A: direct LDG.128 fragments (one-ks-ahead register prefetch; rows >=736
//    read zero-initialized slots). B: 4-stage cp.async smem.
// ===========================================================================
#define B_STAGE_B  18432            // 128*144
#define GEMM_SMEM  (4 * B_STAGE_B)  // 73728

__global__ void __launch_bounds__(256, 2) gemm_kernel()
{
    extern __shared__ char smem[];
    const uint32_t sb = smem_u32(smem);
    const int tid = threadIdx.x;
    const int lane = tid & 31, wid = tid >> 5;
    const int Nt = blockIdx.x, Mt = blockIdx.y, sp = blockIdx.z;
    const int wm = wid & 3, wn = wid >> 2;   // warp tile: rows wm*32, cols wn*64
    const int g = lane >> 2, t4 = lane & 3;

    // ---- B cp.async mapping: 4 chunks (16B) per thread per tile ----
    const int lr = tid >> 3;         // 0..31
    const int lc = tid & 7;          // 0..7
    const __half* gB0[4];
#pragma unroll
    for (int j = 0; j < 4; j++) {
        int n = Nt * 128 + lr + 32 * j;
        gB0[j] = g_xp16 + (size_t)(n / 23) * 147456 + (n % 23) * 384 + lc * 8;
    }
    const uint32_t dOff = (uint32_t)(lr * 144 + lc * 16);

    // ---- A fragment pointers (per warp, mt = 0/1) ----
    const uint4* pA0 = g_Af + ((size_t)(Mt * 8 + wm * 2 + 0) * K_ITERS64) * 128 + lane;
    const uint4* pA1 = g_Af + ((size_t)(Mt * 8 + wm * 2 + 1) * K_ITERS64) * 128 + lane;

    const int k0 = sp * IPS;
    const int k1 = (k0 + IPS < K_ITERS64) ? (k0 + IPS) : K_ITERS64;

#define LOAD_B(kt, b) do {                                                     \
        size_t _ko = (size_t)(kt) * 64;                                        \
        uint32_t _bB = sb + (b) * B_STAGE_B;                                   \
        _Pragma("unroll")                                                      \
        for (int _j = 0; _j < 4; _j++)                                         \
            CP_ASYNC16(_bB + dOff + _j * (32 * 144), gB0[_j] + _ko);           \
    } while (0)

    LOAD_B(k0,     (k0) & 3);     CP_COMMIT();
    LOAD_B(k0 + 1, (k0 + 1) & 3); CP_COMMIT();
    LOAD_B(k0 + 2, (k0 + 2) & 3); CP_COMMIT();

    float acc[2][8][4];
#pragma unroll
    for (int mt = 0; mt < 2; mt++)
#pragma unroll
        for (int nt = 0; nt < 8; nt++)
#pragma unroll
            for (int e = 0; e < 4; e++) acc[mt][nt][e] = 0.f;

    // ---- per-lane ldmatrix offset for B (bytes) ----
    const int matq = lane >> 3, rin = lane & 7;
    const uint32_t offB = (uint32_t)((((matq >> 1) * 8 + rin) * 144) + (matq & 1) * 16);
    const uint32_t bRow = (uint32_t)(wn * 64) * 144;

    uint32_t Bf[4][4];
    uint4 Acur0, Acur1, Anxt0, Anxt1;

    // prologue: A fragments for (k0, ks=0)
    Acur0 = __ldg(pA0 + ((size_t)k0 * 4 + 0) * 32);
    Acur1 = __ldg(pA1 + ((size_t)k0 * 4 + 0) * 32);

    for (int kt = k0; kt < k1; kt++) {
        CP_WAIT2();          // tile kt resident (kt+1, kt+2 may be in flight)
        __syncthreads();     // all warps done reading slot (kt+3)&3's old tile
        if (kt + 3 < k1) LOAD_B(kt + 3, (kt + 3) & 3);
        CP_COMMIT();         // unconditional (possibly empty group)

        const uint32_t cB = sb + (kt & 3) * B_STAGE_B;

#pragma unroll
        for (int ks = 0; ks < 4; ks++) {
            // prefetch next A fragments (next ks, or next kt's ks=0)
            {
                int nkt = (ks < 3) ? kt : ((kt + 1 < k1) ? kt + 1 : kt);
                int nks = (ks + 1) & 3;
                size_t aoff = ((size_t)nkt * 4 + nks) * 32;
                Anxt0 = __ldg(pA0 + aoff);
                Anxt1 = __ldg(pA1 + aoff);
            }
#pragma unroll
            for (int p = 0; p < 4; p++)
                LDSM4(Bf[p][0], Bf[p][1], Bf[p][2], Bf[p][3],
                      cB + bRow + p * (16 * 144) + ks * 32 + offB);
#pragma unroll
            for (int p = 0; p < 4; p++) {
                MMA16816(acc[0][2 * p],     Acur0.x, Acur0.y, Acur0.z, Acur0.w,
                         Bf[p][0], Bf[p][1]);
                MMA16816(acc[0][2 * p + 1], Acur0.x, Acur0.y, Acur0.z, Acur0.w,
                         Bf[p][2], Bf[p][3]);
                MMA16816(acc[1][2 * p],     Acur1.x, Acur1.y, Acur1.z, Acur1.w,
                         Bf[p][0], Bf[p][1]);
                MMA16816(acc[1][2 * p + 1], Acur1.x, Acur1.y, Acur1.z, Acur1.w,
                         Bf[p][2], Bf[p][3]);
            }
            Acur0 = Anxt0;
            Acur1 = Anxt1;
        }
    }

    // ---- epilogue: atomicAdd into g_acc (split-K reduction) ----
    const int row0 = Mt * 128 + wm * 32;
    const int col0 = Nt * 128 + wn * 64;
#pragma unroll
    for (int mt = 0; mt < 2; mt++) {
        int r_lo = row0 + mt * 16 + g;
        int r_hi = r_lo + 8;
#pragma unroll
        for (int nt = 0; nt < 8; nt++) {
            int c = col0 + nt * 8 + 2 * t4;
            bool c0ok = (c < 736), c1ok = (c + 1 < 736);
            if (r_lo < 736) {
                if (c0ok) atomicAdd(&g_acc[r_lo * 768 + c],     acc[mt][nt][0]);
                if (c1ok) atomicAdd(&g_acc[r_lo * 768 + c + 1], acc[mt][nt][1]);
            }
            if (r_hi < 736) {
                if (c0ok) atomicAdd(&g_acc[r_hi * 768 + c],     acc[mt][nt][2]);
                if (c1ok) atomicAdd(&g_acc[r_hi * 768 + c + 1], acc[mt][nt][3]);
            }
        }
    }
#undef LOAD_B
}

// ===========================================================================
// Kernel 5: assemble x2 from g_acc with permutation + scale
// ===========================================================================
__global__ void assemble_kernel(float* __restrict__ out_x2)
{
    int i = blockIdx.x * 256 + threadIdx.x;
    if (i >= 32 * 32 * 23 * 23) return;
    int w = i % 23;
    int t = i / 23;
    int h = t % 23; t /= 23;
    int d = t % 32;
    int o = t / 32;
    out_x2[i] = g_acc[(o * 23 + w) * 768 + (d * 23 + h)] * (1.0f / 131044.0f);
}

// ===========================================================================
// Launch
// ===========================================================================
extern "C" void kernel_launch(void* const* d_in, const int* in_sizes, int n_in,
                              void* d_out, int out_size)
{
    const float* x  = (const float*)d_in[0];
    const float* xp = (const float*)d_in[1];
    float* out = (float*)d_out;

    void *aft = nullptr, *afn = nullptr, *aacc = nullptr;
    cudaGetSymbolAddress(&aft, c_ft);
    cudaGetSymbolAddress(&afn, c_fn);
    cudaGetSymbolAddress(&aacc, g_acc);
    cudaMemcpyAsync(aft, d_in[2], 5808 * sizeof(float), cudaMemcpyDeviceToDevice, 0);
    cudaMemcpyAsync(afn, d_in[3], 1936 * sizeof(float), cudaMemcpyDeviceToDevice, 0);
    cudaMemsetAsync(aacc, 0, 768 * 768 * sizeof(float), 0);

    dim3 g1(6, 48, 2);
    feat_kernel<<<g1, 256>>>(x, xp);

    norm_kernel<<<(2 * 147456 + 255) / 256, 256>>>(out);

    dim3 g3(K_ITERS64, N_MCHUNK);
    packA_kernel<<<g3, 128>>>(out);

    static bool attr_set = false;
    if (!attr_set) {
        cudaFuncSetAttribute(gemm_kernel, cudaFuncAttributeMaxDynamicSharedMemorySize,
                             GEMM_SMEM);
        attr_set = true;
    }
    dim3 g4(6, 6, SPLITS);
    gemm_kernel<<<g4, 256, GEMM_SMEM>>>();

    assemble_kernel<<<(32 * 32 * 23 * 23 + 255) / 256, 256>>>(out + X1_ELEMS);
}